// round 15
// baseline (speedup 1.0000x reference)
#include <cuda_runtime.h>
#include <cuda_fp16.h>
#include <math.h>
#include <cstdint>

#define Bb 16
#define Ss 8192
#define Hh 256

constexpr int CTX_ELEMS = Bb * Hh;
constexpr int ATT_OFF   = CTX_ELEMS;
constexpr int NTILES    = Bb * 64;     // 1024
constexpr int NCTA      = 148;

// -------- scratch --------
__device__ float g_qproj[Bb * Hh];
__device__ float g_maxv[Bb];
__device__ float g_invsum[Bb];
__device__ float g_ctxpart[Bb * 64 * Hh];
__device__ float g_blkmax[NTILES];
__device__ float g_blksum[NTILES];
__device__ __half g_Bh[Hh * Hh];
__device__ __half g_Bl[Hh * Hh];
__device__ unsigned int g_ticket;
__device__ unsigned int g_ticket_b[Bb];
__device__ volatile unsigned int g_flag;

// ---------------- helpers ----------------
__device__ __forceinline__ uint32_t smem_u32(const void* p) {
    uint32_t a;
    asm("{ .reg .u64 t; cvta.to.shared.u64 t, %1; cvt.u32.u64 %0, t; }" : "=r"(a) : "l"(p));
    return a;
}
__device__ __forceinline__ void ldmx4(uint32_t& r0, uint32_t& r1, uint32_t& r2, uint32_t& r3,
                                      uint32_t addr) {
    asm volatile("ldmatrix.sync.aligned.m8n8.x4.shared.b16 {%0,%1,%2,%3}, [%4];"
                 : "=r"(r0), "=r"(r1), "=r"(r2), "=r"(r3) : "r"(addr));
}
__device__ __forceinline__ void mma_f32(float* d, const uint32_t* a, const uint32_t* b) {
    asm volatile("mma.sync.aligned.m16n8k16.row.col.f32.f16.f16.f32 "
                 "{%0,%1,%2,%3}, {%4,%5,%6,%7}, {%8,%9}, {%0,%1,%2,%3};"
                 : "+f"(d[0]), "+f"(d[1]), "+f"(d[2]), "+f"(d[3])
                 : "r"(a[0]), "r"(a[1]), "r"(a[2]), "r"(a[3]), "r"(b[0]), "r"(b[1]));
}
__device__ __forceinline__ void cp16(uint32_t dst, const void* src) {
    asm volatile("cp.async.cg.shared.global [%0], [%1], 16;" :: "r"(dst), "l"(src) : "memory");
}
#define CP_COMMIT() asm volatile("cp.async.commit_group;" ::: "memory")
#define CP_WAIT0()  asm volatile("cp.async.wait_group 0;" ::: "memory")

__device__ __forceinline__ float tanh_fast(float x) {
    float t, r;
    asm("ex2.approx.f32 %0, %1;" : "=f"(t) : "f"(x * 2.8853900817779268f));
    asm("rcp.approx.f32 %0, %1;" : "=f"(r) : "f"(t + 1.0f));
    return fmaf(-2.0f, r, 1.0f);
}

// ---------------- prep: Wk split + q projection + ticket reset ----------------
__global__ void k_prep(const float* __restrict__ W, const float* __restrict__ q,
                       const float* __restrict__ bvec) {
    if (blockIdx.x == 0) {
        if (threadIdx.x == 0) { g_ticket = 0u; g_flag = 0u; }
        if (threadIdx.x < Bb) g_ticket_b[threadIdx.x] = 0u;
    }
    if (blockIdx.x < 256) {
        int o = blockIdx.x, k = threadIdx.x;
        float x = W[o * (2 * Hh) + Hh + k];
        __half hi = __float2half_rn(x);
        __half lo = __float2half_rn(x - __half2float(hi));
        g_Bh[o * Hh + k] = hi;
        g_Bl[o * Hh + k] = lo;
    } else {
        __shared__ float sq[Hh];
        int b = blockIdx.x - 256, o = threadIdx.x;
        sq[o] = q[b * Hh + o];
        __syncthreads();
        float s = bvec[o];
        const float* row = W + o * (2 * Hh);
#pragma unroll 8
        for (int h = 0; h < Hh; ++h) s += sq[h] * row[h];
        g_qproj[b * Hh + o] = s;
    }
}

// ---------------- main persistent kernel: GEMM + softmax + context ----------------
#define AST 72
constexpr int AREG = 0;          // A: 2 buf x 2 split x 18432 = 73728 (reused as phase-2 scratch)
constexpr int BREG = 73728;      // B: 2 buf x 2 split x 36864 = 147456
constexpr int QSH_OFF = 221184;  // 256 f
constexpr int VSH_OFF = 222208;  // 256 f
constexpr int SCB_OFF = 223232;  // 768 f
constexpr int SMEM_BYTES = 226304;

__device__ __forceinline__ uint32_t a_off(int buf, int split) {
    return AREG + (buf * 2 + split) * 18432;
}
__device__ __forceinline__ uint32_t b_off(int buf, int split) {
    return BREG + (buf * 2 + split) * 36864;
}

__global__ void __launch_bounds__(512, 1)
k_scores_mma(const float* __restrict__ key, const float* __restrict__ value,
             const float* __restrict__ vvec, float* __restrict__ out) {
    extern __shared__ char smem[];
    const uint32_t sbase = smem_u32(smem);

    const int tid  = threadIdx.x;
    const int wid  = tid >> 5;
    const int lane = tid & 31;
    const int wr   = wid >> 2;
    const int wc   = wid & 3;
    const int bid  = blockIdx.x;

    float* qsh = (float*)(smem + QSH_OFF);
    float* vsh = (float*)(smem + VSH_OFF);
    float* scb = (float*)(smem + SCB_OFF);

    if (tid < 256) vsh[tid] = vvec[tid];

    float acc[2][8][4];
#pragma unroll
    for (int mt = 0; mt < 2; ++mt)
#pragma unroll
        for (int nt = 0; nt < 8; ++nt)
#pragma unroll
            for (int i = 0; i < 4; ++i) acc[mt][nt][i] = 0.f;

    const int quad = lane >> 3;
    const int lr   = lane & 7;

    const int sa_r0 = tid >> 4;
    const int sa_k4 = (tid & 15) * 4;
    const int sb_n  = tid >> 3;
    const int sb_k8 = (tid & 7) * 8;

    float4 pA[4];

    auto ldA = [&](int tile, int c) {
        const float* kb = key + ((long long)((tile >> 6) * Ss + (tile & 63) * 128)) * Hh;
#pragma unroll
        for (int pass = 0; pass < 4; ++pass) {
            int r = sa_r0 + pass * 32;
            pA[pass] = __ldg((const float4*)(kb + (long long)r * Hh + c * 64 + sa_k4));
        }
    };
    auto stA = [&](int bb) {
        __half* Ah = (__half*)(smem + a_off(bb, 0));
        __half* Al = (__half*)(smem + a_off(bb, 1));
#pragma unroll
        for (int pass = 0; pass < 4; ++pass) {
            int r = sa_r0 + pass * 32;
            float4 x = pA[pass];
            __half2 h01 = __floats2half2_rn(x.x, x.y);
            __half2 h23 = __floats2half2_rn(x.z, x.w);
            float2 f01 = __half22float2(h01);
            float2 f23 = __half22float2(h23);
            __half2 l01 = __floats2half2_rn(x.x - f01.x, x.y - f01.y);
            __half2 l23 = __floats2half2_rn(x.z - f23.x, x.w - f23.y);
            *(uint2*)(Ah + r * AST + sa_k4) = make_uint2(*(uint32_t*)&h01, *(uint32_t*)&h23);
            *(uint2*)(Al + r * AST + sa_k4) = make_uint2(*(uint32_t*)&l01, *(uint32_t*)&l23);
        }
    };
    auto stageB = [&](int c, int bb) {
        uint32_t dh = sbase + b_off(bb, 0);
        uint32_t dl = sbase + b_off(bb, 1);
#pragma unroll
        for (int pass = 0; pass < 4; ++pass) {
            int n = sb_n + pass * 64;
            uint32_t doff = (uint32_t)(n * AST + sb_k8) * 2u;
            cp16(dh + doff, g_Bh + n * Hh + c * 64 + sb_k8);
            cp16(dl + doff, g_Bl + n * Hh + c * 64 + sb_k8);
        }
        CP_COMMIT();
    };

    const int ntile = (NTILES - bid + NCTA - 1) / NCTA;
    const int nseq  = ntile * 4;

    stageB(0, 0);
    ldA(bid, 0);
    stA(0);
    CP_WAIT0();
    __syncthreads();

    for (int seq = 0; seq < nseq; ++seq) {
        const int c    = seq & 3;
        const int buf  = seq & 1;
        const int tile = bid + (seq >> 2) * NCTA;

        if (seq + 1 < nseq) {
            stageB((seq + 1) & 3, buf ^ 1);
            ldA(bid + ((seq + 1) >> 2) * NCTA, (seq + 1) & 3);
        }

        const uint32_t ah_base = sbase + a_off(buf, 0);
        const uint32_t al_base = sbase + a_off(buf, 1);
        const uint32_t bh_base = sbase + b_off(buf, 0);
        const uint32_t bl_base = sbase + b_off(buf, 1);

#pragma unroll
        for (int ks = 0; ks < 4; ++ks) {
            const int acol = ks * 16 + (quad >> 1) * 8;
            const int bcol = ks * 16 + (quad & 1) * 8;

            uint32_t bf[8][2];
#pragma unroll
            for (int ng = 0; ng < 4; ++ng) {
                int brow = wc * 64 + ng * 16 + (quad >> 1) * 8 + lr;
                uint32_t r0, r1, r2, r3;
                ldmx4(r0, r1, r2, r3, bh_base + (uint32_t)(brow * AST + bcol) * 2u);
                bf[2 * ng][0] = r0; bf[2 * ng][1] = r1;
                bf[2 * ng + 1][0] = r2; bf[2 * ng + 1][1] = r3;
            }
            uint32_t ah[2][4];
#pragma unroll
            for (int mt = 0; mt < 2; ++mt) {
                int arow = wr * 32 + mt * 16 + (quad & 1) * 8 + lr;
                ldmx4(ah[mt][0], ah[mt][1], ah[mt][2], ah[mt][3],
                      ah_base + (uint32_t)(arow * AST + acol) * 2u);
            }
#pragma unroll
            for (int mt = 0; mt < 2; ++mt)
#pragma unroll
                for (int nt = 0; nt < 8; ++nt)
                    mma_f32(acc[mt][nt], ah[mt], bf[nt]);
            {
                uint32_t al[4];
#pragma unroll
                for (int mt = 0; mt < 2; ++mt) {
                    int arow = wr * 32 + mt * 16 + (quad & 1) * 8 + lr;
                    ldmx4(al[0], al[1], al[2], al[3],
                          al_base + (uint32_t)(arow * AST + acol) * 2u);
#pragma unroll
                    for (int nt = 0; nt < 8; ++nt)
                        mma_f32(acc[mt][nt], al, bf[nt]);
                }
            }
#pragma unroll
            for (int ng = 0; ng < 4; ++ng) {
                int brow = wc * 64 + ng * 16 + (quad >> 1) * 8 + lr;
                uint32_t r0, r1, r2, r3;
                ldmx4(r0, r1, r2, r3, bl_base + (uint32_t)(brow * AST + bcol) * 2u);
                bf[2 * ng][0] = r0; bf[2 * ng][1] = r1;
                bf[2 * ng + 1][0] = r2; bf[2 * ng + 1][1] = r3;
            }
#pragma unroll
            for (int mt = 0; mt < 2; ++mt)
#pragma unroll
                for (int nt = 0; nt < 8; ++nt)
                    mma_f32(acc[mt][nt], ah[mt], bf[nt]);
        }

        if (seq + 1 < nseq) stA(buf ^ 1);
        CP_WAIT0();
        __syncthreads();

        if (c == 3) {
            // ---- epilogue for this tile ----
            const int b  = tile >> 6;
            const int s0 = (tile & 63) * 128;

            if (tid < 256) qsh[tid] = __ldg(g_qproj + b * Hh + tid);
            __syncthreads();

            const int g  = lane >> 2;
            const int tg = lane & 3;
            float part[4] = {0.f, 0.f, 0.f, 0.f};
#pragma unroll
            for (int mt = 0; mt < 2; ++mt)
#pragma unroll
                for (int nt = 0; nt < 8; ++nt) {
                    int col0 = wc * 64 + nt * 8 + tg * 2;
                    float2 qp = *(float2*)(qsh + col0);
                    float2 vp = *(float2*)(vsh + col0);
#pragma unroll
                    for (int i = 0; i < 4; ++i) {
                        float qv = (i & 1) ? qp.y : qp.x;
                        float vv = (i & 1) ? vp.y : vp.x;
                        part[mt * 2 + (i >> 1)] += tanh_fast(acc[mt][nt][i] + qv) * vv;
                    }
                }
#pragma unroll
            for (int p = 0; p < 4; ++p) {
                part[p] += __shfl_xor_sync(0xffffffffu, part[p], 1);
                part[p] += __shfl_xor_sync(0xffffffffu, part[p], 2);
            }
            if (tg == 0) {
#pragma unroll
                for (int mt = 0; mt < 2; ++mt)
#pragma unroll
                    for (int h = 0; h < 2; ++h) {
                        int row = wr * 32 + mt * 16 + h * 8 + g;
                        scb[128 + row * 4 + wc] = part[mt * 2 + h];
                    }
            }
            __syncthreads();
            if (tid < 128) {
                float s = scb[128 + tid * 4] + scb[128 + tid * 4 + 1]
                        + scb[128 + tid * 4 + 2] + scb[128 + tid * 4 + 3];
                scb[tid] = s;
                out[ATT_OFF + b * Ss + s0 + tid] = s;
            }
            __syncthreads();
            if (tid < 32) {
                float m = fmaxf(fmaxf(scb[tid], scb[tid + 32]),
                                fmaxf(scb[tid + 64], scb[tid + 96]));
#pragma unroll
                for (int off = 16; off; off >>= 1)
                    m = fmaxf(m, __shfl_xor_sync(0xffffffffu, m, off));
                float e = expf(scb[tid] - m) + expf(scb[tid + 32] - m)
                        + expf(scb[tid + 64] - m) + expf(scb[tid + 96] - m);
#pragma unroll
                for (int off = 16; off; off >>= 1)
                    e += __shfl_xor_sync(0xffffffffu, e, off);
                if (lane == 0) { g_blkmax[tile] = m; g_blksum[tile] = e; }
            }
#pragma unroll
            for (int mt = 0; mt < 2; ++mt)
#pragma unroll
                for (int nt = 0; nt < 8; ++nt)
#pragma unroll
                    for (int i = 0; i < 4; ++i) acc[mt][nt][i] = 0.f;
        }
    }

    // ---- device-wide barrier: last CTA combines, then releases everyone ----
    __threadfence();
    __shared__ unsigned int rank_s;
    if (tid == 0) rank_s = atomicAdd(&g_ticket, 1u);
    __syncthreads();
    if (rank_s == NCTA - 1) {
        __threadfence();
        if (wid < 16) {
            int bb = wid;
            float m0 = g_blkmax[bb * 64 + lane];
            float m1 = g_blkmax[bb * 64 + 32 + lane];
            float m = fmaxf(m0, m1);
#pragma unroll
            for (int off = 16; off; off >>= 1)
                m = fmaxf(m, __shfl_xor_sync(0xffffffffu, m, off));
            float e = g_blksum[bb * 64 + lane] * expf(m0 - m)
                    + g_blksum[bb * 64 + 32 + lane] * expf(m1 - m);
#pragma unroll
            for (int off = 16; off; off >>= 1)
                e += __shfl_xor_sync(0xffffffffu, e, off);
            if (lane == 0) { g_maxv[bb] = m; g_invsum[bb] = 1.f / e; }
        }
        __syncthreads();
        if (tid == 0) { __threadfence(); g_flag = 1u; }
    }
    if (tid == 0) {
        while (g_flag == 0u) __nanosleep(64);
    }
    __syncthreads();

    // ---- phase 2: normalize weights + context (grid-stride over 1024 chunks) ----
    float*  swA  = scb;                         // 128 weights
    float4* red4 = (float4*)(smem + AREG);      // 8 KB scratch (A region is dead)

    for (int chunk = bid; chunk < NTILES; chunk += NCTA) {
        const int b   = chunk >> 6;
        const int ch  = chunk & 63;
        const int s0c = ch * 128;
        const float mx = g_maxv[b], is = g_invsum[b];
        float* att = out + ATT_OFF + (long long)b * Ss;

        if (tid < 128) {
            float w = expf(att[s0c + tid] - mx) * is;
            att[s0c + tid] = w;
            swA[tid] = w;
        }
        __syncthreads();

        const int c4  = (tid & 63) * 4;
        const int rg8 = tid >> 6;               // 0..7, 16 rows each
        const float* vb  = value + ((long long)(b * Ss + s0c + rg8 * 16)) * Hh + c4;
        const float* swp = swA + rg8 * 16;

        float4 a = make_float4(0.f, 0.f, 0.f, 0.f);
#pragma unroll
        for (int r = 0; r < 16; ++r) {
            float w = swp[r];
            float4 v4 = __ldg((const float4*)(vb + (long long)r * Hh));
            a.x += w * v4.x; a.y += w * v4.y; a.z += w * v4.z; a.w += w * v4.w;
        }
        red4[tid] = a;
        __syncthreads();
        if (rg8 == 0) {
#pragma unroll
            for (int gg = 1; gg < 8; ++gg) {
                float4 p = red4[tid + gg * 64];
                a.x += p.x; a.y += p.y; a.z += p.z; a.w += p.w;
            }
            *(float4*)(g_ctxpart + ((long long)chunk * Hh + c4)) = a;
        }
        __threadfence();
        __syncthreads();
        if (tid == 0) rank_s = atomicAdd(&g_ticket_b[b], 1u);
        __syncthreads();
        if (rank_s == 63u) {
            __threadfence();
            float4 s = make_float4(0.f, 0.f, 0.f, 0.f);
#pragma unroll
            for (int cc = 0; cc < 8; ++cc) {
                float4 p = *(const float4*)(g_ctxpart +
                            ((long long)(b * 64 + rg8 * 8 + cc) * Hh + c4));
                s.x += p.x; s.y += p.y; s.z += p.z; s.w += p.w;
            }
            __syncthreads();
            red4[tid] = s;
            __syncthreads();
            if (rg8 == 0) {
#pragma unroll
                for (int gg = 1; gg < 8; ++gg) {
                    float4 p = red4[tid + gg * 64];
                    s.x += p.x; s.y += p.y; s.z += p.z; s.w += p.w;
                }
                *(float4*)(out + b * Hh + c4) = s;
            }
        }
        __syncthreads();
    }
}

// ---------------- launch ----------------
extern "C" void kernel_launch(void* const* d_in, const int* in_sizes, int n_in,
                              void* d_out, int out_size) {
    const float* query  = (const float*)d_in[0];
    const float* key    = (const float*)d_in[1];
    const float* value  = (const float*)d_in[2];
    const float* W_attn = (const float*)d_in[3];
    const float* b_attn = (const float*)d_in[4];
    const float* v      = (const float*)d_in[5];
    float* out = (float*)d_out;

    cudaFuncSetAttribute(k_scores_mma, cudaFuncAttributeMaxDynamicSharedMemorySize, SMEM_BYTES);

    k_prep<<<272, 256>>>(W_attn, query, b_attn);
    k_scores_mma<<<NCTA, 512, SMEM_BYTES>>>(key, value, v, out);
}

// round 16
// speedup vs baseline: 1.1034x; 1.1034x over previous
#include <cuda_runtime.h>
#include <cuda_fp16.h>
#include <math.h>
#include <cstdint>

#define Bb 16
#define Ss 8192
#define Hh 256

constexpr int CTX_ELEMS = Bb * Hh;
constexpr int ATT_OFF   = CTX_ELEMS;
constexpr int NTILES    = Bb * 64;     // 1024
constexpr int NCTA      = 148;

// -------- scratch --------
__device__ float g_qproj[Bb * Hh];
__device__ float g_maxv[Bb];
__device__ float g_invsum[Bb];
__device__ float g_ctxpart[Bb * 64 * Hh];
__device__ float g_blkmax[NTILES];
__device__ float g_blksum[NTILES];
__device__ __half g_Bh[Hh * Hh];
__device__ __half g_Bl[Hh * Hh];
__device__ unsigned int g_ticket;
__device__ unsigned int g_ticket_b[Bb];

// ---------------- helpers ----------------
__device__ __forceinline__ uint32_t smem_u32(const void* p) {
    uint32_t a;
    asm("{ .reg .u64 t; cvta.to.shared.u64 t, %1; cvt.u32.u64 %0, t; }" : "=r"(a) : "l"(p));
    return a;
}
__device__ __forceinline__ void ldmx4(uint32_t& r0, uint32_t& r1, uint32_t& r2, uint32_t& r3,
                                      uint32_t addr) {
    asm volatile("ldmatrix.sync.aligned.m8n8.x4.shared.b16 {%0,%1,%2,%3}, [%4];"
                 : "=r"(r0), "=r"(r1), "=r"(r2), "=r"(r3) : "r"(addr));
}
__device__ __forceinline__ void mma_f32(float* d, const uint32_t* a, const uint32_t* b) {
    asm volatile("mma.sync.aligned.m16n8k16.row.col.f32.f16.f16.f32 "
                 "{%0,%1,%2,%3}, {%4,%5,%6,%7}, {%8,%9}, {%0,%1,%2,%3};"
                 : "+f"(d[0]), "+f"(d[1]), "+f"(d[2]), "+f"(d[3])
                 : "r"(a[0]), "r"(a[1]), "r"(a[2]), "r"(a[3]), "r"(b[0]), "r"(b[1]));
}
__device__ __forceinline__ void cp16(uint32_t dst, const void* src) {
    asm volatile("cp.async.cg.shared.global [%0], [%1], 16;" :: "r"(dst), "l"(src) : "memory");
}
#define CP_COMMIT() asm volatile("cp.async.commit_group;" ::: "memory")
#define CP_WAIT0()  asm volatile("cp.async.wait_group 0;" ::: "memory")

__device__ __forceinline__ float tanh_fast(float x) {
    float t, r;
    asm("ex2.approx.f32 %0, %1;" : "=f"(t) : "f"(x * 2.8853900817779268f));
    asm("rcp.approx.f32 %0, %1;" : "=f"(r) : "f"(t + 1.0f));
    return fmaf(-2.0f, r, 1.0f);
}

// ---------------- prep: Wk split + q projection + ticket reset ----------------
__global__ void k_prep(const float* __restrict__ W, const float* __restrict__ q,
                       const float* __restrict__ bvec) {
    if (blockIdx.x == 0) {
        if (threadIdx.x == 0) g_ticket = 0u;
        if (threadIdx.x < Bb) g_ticket_b[threadIdx.x] = 0u;
    }
    if (blockIdx.x < 256) {
        int o = blockIdx.x, k = threadIdx.x;
        float x = W[o * (2 * Hh) + Hh + k];
        __half hi = __float2half_rn(x);
        __half lo = __float2half_rn(x - __half2float(hi));
        g_Bh[o * Hh + k] = hi;
        g_Bl[o * Hh + k] = lo;
    } else {
        __shared__ float sq[Hh];
        int b = blockIdx.x - 256, o = threadIdx.x;
        sq[o] = q[b * Hh + o];
        __syncthreads();
        float s = bvec[o];
        const float* row = W + o * (2 * Hh);
#pragma unroll 8
        for (int h = 0; h < Hh; ++h) s += sq[h] * row[h];
        g_qproj[b * Hh + o] = s;
    }
}

// ---------------- main persistent GEMM kernel ----------------
#define AST 72
constexpr int AREG = 0;          // A: 2 buf x 2 split x 18432 = 73728
constexpr int BREG = 73728;      // B: 2 buf x 2 split x 36864 = 147456
constexpr int QSH_OFF = 221184;  // 256 f
constexpr int VSH_OFF = 222208;  // 256 f
constexpr int SCB_OFF = 223232;  // 768 f
constexpr int SMEM_BYTES = 226304;

__device__ __forceinline__ uint32_t a_off(int buf, int split) {
    return AREG + (buf * 2 + split) * 18432;
}
__device__ __forceinline__ uint32_t b_off(int buf, int split) {
    return BREG + (buf * 2 + split) * 36864;
}

__global__ void __launch_bounds__(512, 1)
k_scores_mma(const float* __restrict__ key, const float* __restrict__ vvec,
             float* __restrict__ out) {
    extern __shared__ char smem[];
    const uint32_t sbase = smem_u32(smem);

    const int tid  = threadIdx.x;
    const int wid  = tid >> 5;
    const int lane = tid & 31;
    const int wr   = wid >> 2;
    const int wc   = wid & 3;
    const int bid  = blockIdx.x;

    float* qsh = (float*)(smem + QSH_OFF);
    float* vsh = (float*)(smem + VSH_OFF);
    float* scb = (float*)(smem + SCB_OFF);

    if (tid < 256) vsh[tid] = vvec[tid];

    float acc[2][8][4];
#pragma unroll
    for (int mt = 0; mt < 2; ++mt)
#pragma unroll
        for (int nt = 0; nt < 8; ++nt)
#pragma unroll
            for (int i = 0; i < 4; ++i) acc[mt][nt][i] = 0.f;

    const int quad = lane >> 3;
    const int lr   = lane & 7;

    const int sa_r0 = tid >> 4;
    const int sa_k4 = (tid & 15) * 4;
    const int sb_n  = tid >> 3;
    const int sb_k8 = (tid & 7) * 8;

    float4 pA[4];

    auto ldA = [&](int tile, int c) {
        const float* kb = key + ((long long)((tile >> 6) * Ss + (tile & 63) * 128)) * Hh;
#pragma unroll
        for (int pass = 0; pass < 4; ++pass) {
            int r = sa_r0 + pass * 32;
            pA[pass] = __ldg((const float4*)(kb + (long long)r * Hh + c * 64 + sa_k4));
        }
    };
    auto stA = [&](int bb) {
        __half* Ah = (__half*)(smem + a_off(bb, 0));
        __half* Al = (__half*)(smem + a_off(bb, 1));
#pragma unroll
        for (int pass = 0; pass < 4; ++pass) {
            int r = sa_r0 + pass * 32;
            float4 x = pA[pass];
            __half2 h01 = __floats2half2_rn(x.x, x.y);
            __half2 h23 = __floats2half2_rn(x.z, x.w);
            float2 f01 = __half22float2(h01);
            float2 f23 = __half22float2(h23);
            __half2 l01 = __floats2half2_rn(x.x - f01.x, x.y - f01.y);
            __half2 l23 = __floats2half2_rn(x.z - f23.x, x.w - f23.y);
            *(uint2*)(Ah + r * AST + sa_k4) = make_uint2(*(uint32_t*)&h01, *(uint32_t*)&h23);
            *(uint2*)(Al + r * AST + sa_k4) = make_uint2(*(uint32_t*)&l01, *(uint32_t*)&l23);
        }
    };
    auto stageB = [&](int c, int bb) {
        uint32_t dh = sbase + b_off(bb, 0);
        uint32_t dl = sbase + b_off(bb, 1);
#pragma unroll
        for (int pass = 0; pass < 4; ++pass) {
            int n = sb_n + pass * 64;
            uint32_t doff = (uint32_t)(n * AST + sb_k8) * 2u;
            cp16(dh + doff, g_Bh + n * Hh + c * 64 + sb_k8);
            cp16(dl + doff, g_Bl + n * Hh + c * 64 + sb_k8);
        }
        CP_COMMIT();
    };

    const int ntile = (NTILES - bid + NCTA - 1) / NCTA;
    const int nseq  = ntile * 4;

    stageB(0, 0);
    ldA(bid, 0);
    stA(0);
    CP_WAIT0();
    __syncthreads();

    for (int seq = 0; seq < nseq; ++seq) {
        const int c    = seq & 3;
        const int buf  = seq & 1;
        const int tile = bid + (seq >> 2) * NCTA;

        if (seq + 1 < nseq) {
            stageB((seq + 1) & 3, buf ^ 1);
            ldA(bid + ((seq + 1) >> 2) * NCTA, (seq + 1) & 3);
        }

        const uint32_t ah_base = sbase + a_off(buf, 0);
        const uint32_t al_base = sbase + a_off(buf, 1);
        const uint32_t bh_base = sbase + b_off(buf, 0);
        const uint32_t bl_base = sbase + b_off(buf, 1);

        auto kstep = [&](int ks) {
            const int acol = ks * 16 + (quad >> 1) * 8;
            const int bcol = ks * 16 + (quad & 1) * 8;

            uint32_t bf[8][2];
#pragma unroll
            for (int ng = 0; ng < 4; ++ng) {
                int brow = wc * 64 + ng * 16 + (quad >> 1) * 8 + lr;
                uint32_t r0, r1, r2, r3;
                ldmx4(r0, r1, r2, r3, bh_base + (uint32_t)(brow * AST + bcol) * 2u);
                bf[2 * ng][0] = r0; bf[2 * ng][1] = r1;
                bf[2 * ng + 1][0] = r2; bf[2 * ng + 1][1] = r3;
            }
            uint32_t ah[2][4];
#pragma unroll
            for (int mt = 0; mt < 2; ++mt) {
                int arow = wr * 32 + mt * 16 + (quad & 1) * 8 + lr;
                ldmx4(ah[mt][0], ah[mt][1], ah[mt][2], ah[mt][3],
                      ah_base + (uint32_t)(arow * AST + acol) * 2u);
            }
#pragma unroll
            for (int mt = 0; mt < 2; ++mt)
#pragma unroll
                for (int nt = 0; nt < 8; ++nt)
                    mma_f32(acc[mt][nt], ah[mt], bf[nt]);
            {
                uint32_t al[4];
#pragma unroll
                for (int mt = 0; mt < 2; ++mt) {
                    int arow = wr * 32 + mt * 16 + (quad & 1) * 8 + lr;
                    ldmx4(al[0], al[1], al[2], al[3],
                          al_base + (uint32_t)(arow * AST + acol) * 2u);
#pragma unroll
                    for (int nt = 0; nt < 8; ++nt)
                        mma_f32(acc[mt][nt], al, bf[nt]);
                }
            }
#pragma unroll
            for (int ng = 0; ng < 4; ++ng) {
                int brow = wc * 64 + ng * 16 + (quad >> 1) * 8 + lr;
                uint32_t r0, r1, r2, r3;
                ldmx4(r0, r1, r2, r3, bl_base + (uint32_t)(brow * AST + bcol) * 2u);
                bf[2 * ng][0] = r0; bf[2 * ng][1] = r1;
                bf[2 * ng + 1][0] = r2; bf[2 * ng + 1][1] = r3;
            }
#pragma unroll
            for (int mt = 0; mt < 2; ++mt)
#pragma unroll
                for (int nt = 0; nt < 8; ++nt)
                    mma_f32(acc[mt][nt], ah[mt], bf[nt]);
        };

        // ks=0 first (covers the LDG latency of ldA), then retire pA early via stA,
        // freeing its 16 registers for the remaining 3/4 of the MMA loop.
        kstep(0);
        if (seq + 1 < nseq) stA(buf ^ 1);
        kstep(1);
        kstep(2);
        kstep(3);

        CP_WAIT0();
        __syncthreads();

        if (c == 3) {
            // ---- epilogue for this tile ----
            const int b  = tile >> 6;
            const int s0 = (tile & 63) * 128;

            if (tid < 256) qsh[tid] = __ldg(g_qproj + b * Hh + tid);
            __syncthreads();

            const int g  = lane >> 2;
            const int tg = lane & 3;
            float part[4] = {0.f, 0.f, 0.f, 0.f};
#pragma unroll
            for (int mt = 0; mt < 2; ++mt)
#pragma unroll
                for (int nt = 0; nt < 8; ++nt) {
                    int col0 = wc * 64 + nt * 8 + tg * 2;
                    float2 qp = *(float2*)(qsh + col0);
                    float2 vp = *(float2*)(vsh + col0);
#pragma unroll
                    for (int i = 0; i < 4; ++i) {
                        float qv = (i & 1) ? qp.y : qp.x;
                        float vv = (i & 1) ? vp.y : vp.x;
                        part[mt * 2 + (i >> 1)] += tanh_fast(acc[mt][nt][i] + qv) * vv;
                    }
                }
#pragma unroll
            for (int p = 0; p < 4; ++p) {
                part[p] += __shfl_xor_sync(0xffffffffu, part[p], 1);
                part[p] += __shfl_xor_sync(0xffffffffu, part[p], 2);
            }
            if (tg == 0) {
#pragma unroll
                for (int mt = 0; mt < 2; ++mt)
#pragma unroll
                    for (int h = 0; h < 2; ++h) {
                        int row = wr * 32 + mt * 16 + h * 8 + g;
                        scb[128 + row * 4 + wc] = part[mt * 2 + h];
                    }
            }
            __syncthreads();
            if (tid < 128) {
                float s = scb[128 + tid * 4] + scb[128 + tid * 4 + 1]
                        + scb[128 + tid * 4 + 2] + scb[128 + tid * 4 + 3];
                scb[tid] = s;
                out[ATT_OFF + b * Ss + s0 + tid] = s;
            }
            __syncthreads();
            if (tid < 32) {
                float m = fmaxf(fmaxf(scb[tid], scb[tid + 32]),
                                fmaxf(scb[tid + 64], scb[tid + 96]));
#pragma unroll
                for (int off = 16; off; off >>= 1)
                    m = fmaxf(m, __shfl_xor_sync(0xffffffffu, m, off));
                float e = expf(scb[tid] - m) + expf(scb[tid + 32] - m)
                        + expf(scb[tid + 64] - m) + expf(scb[tid + 96] - m);
#pragma unroll
                for (int off = 16; off; off >>= 1)
                    e += __shfl_xor_sync(0xffffffffu, e, off);
                if (lane == 0) { g_blkmax[tile] = m; g_blksum[tile] = e; }
            }
#pragma unroll
            for (int mt = 0; mt < 2; ++mt)
#pragma unroll
                for (int nt = 0; nt < 8; ++nt)
#pragma unroll
                    for (int i = 0; i < 4; ++i) acc[mt][nt][i] = 0.f;
        }
    }

    // ---- last-arriving CTA performs the softmax combine ----
    __threadfence();
    __shared__ unsigned int rank_s;
    if (tid == 0) rank_s = atomicAdd(&g_ticket, 1u);
    __syncthreads();
    if (rank_s == NCTA - 1) {
        __threadfence();
        if (wid < 16) {
            int bb = wid;
            float m0 = g_blkmax[bb * 64 + lane];
            float m1 = g_blkmax[bb * 64 + 32 + lane];
            float m = fmaxf(m0, m1);
#pragma unroll
            for (int off = 16; off; off >>= 1)
                m = fmaxf(m, __shfl_xor_sync(0xffffffffu, m, off));
            float e = g_blksum[bb * 64 + lane] * expf(m0 - m)
                    + g_blksum[bb * 64 + 32 + lane] * expf(m1 - m);
#pragma unroll
            for (int off = 16; off; off >>= 1)
                e += __shfl_xor_sync(0xffffffffu, e, off);
            if (lane == 0) { g_maxv[bb] = m; g_invsum[bb] = 1.f / e; }
        }
    }
}

// ---------------- normalize weights + partial context + folded final reduce ----
#define DCH 128
__global__ void __launch_bounds__(256)
k_context(const float* __restrict__ value, float* __restrict__ out) {
    __shared__ float sw[DCH];
    __shared__ float4 red[256];
    __shared__ unsigned int rank_s;
    int b  = blockIdx.x >> 6;
    int ch = blockIdx.x & 63;
    int s0 = ch * DCH;
    int t  = threadIdx.x;          // 256
    float mx = g_maxv[b], is = g_invsum[b];
    float* att = out + ATT_OFF + b * Ss;
    if (t < DCH) {
        float w = expf(att[s0 + t] - mx) * is;
        att[s0 + t] = w;
        sw[t] = w;
    }
    __syncthreads();

    const int c4 = (t & 63) * 4;
    const int rg = t >> 6;                 // 0..3, 32 rows each
    const float* vb = value + ((long long)(b * Ss + s0 + rg * 32)) * Hh + c4;
    const float* swp = sw + rg * 32;

    float4 a0 = make_float4(0.f, 0.f, 0.f, 0.f);
    float4 a1 = make_float4(0.f, 0.f, 0.f, 0.f);
#pragma unroll 8
    for (int r = 0; r < 32; r += 2) {
        float w0 = swp[r], w1 = swp[r + 1];
        float4 v0 = __ldg((const float4*)(vb + (long long)r * Hh));
        float4 v1 = __ldg((const float4*)(vb + (long long)(r + 1) * Hh));
        a0.x += w0 * v0.x; a0.y += w0 * v0.y; a0.z += w0 * v0.z; a0.w += w0 * v0.w;
        a1.x += w1 * v1.x; a1.y += w1 * v1.y; a1.z += w1 * v1.z; a1.w += w1 * v1.w;
    }
    float4 a = make_float4(a0.x + a1.x, a0.y + a1.y, a0.z + a1.z, a0.w + a1.w);
    red[t] = a;
    __syncthreads();
    if (rg == 0) {
        float4 r1 = red[t + 64], r2 = red[t + 128], r3 = red[t + 192];
        a.x += r1.x + r2.x + r3.x;
        a.y += r1.y + r2.y + r3.y;
        a.z += r1.z + r2.z + r3.z;
        a.w += r1.w + r2.w + r3.w;
        *(float4*)(g_ctxpart + ((long long)(b * 64 + ch) * Hh + c4)) = a;
    }
    // ---- per-batch ticket: last block reduces the 64 partials ----
    __threadfence();
    __syncthreads();
    if (t == 0) rank_s = atomicAdd(&g_ticket_b[b], 1u);
    __syncthreads();
    if (rank_s == 63u) {
        __threadfence();
        float4 s = make_float4(0.f, 0.f, 0.f, 0.f);
#pragma unroll
        for (int cc = 0; cc < 16; ++cc) {
            float4 p = *(const float4*)(g_ctxpart +
                        ((long long)(b * 64 + rg * 16 + cc) * Hh + c4));
            s.x += p.x; s.y += p.y; s.z += p.z; s.w += p.w;
        }
        __syncthreads();
        red[t] = s;
        __syncthreads();
        if (rg == 0) {
            float4 r1 = red[t + 64], r2 = red[t + 128], r3 = red[t + 192];
            s.x += r1.x + r2.x + r3.x;
            s.y += r1.y + r2.y + r3.y;
            s.z += r1.z + r2.z + r3.z;
            s.w += r1.w + r2.w + r3.w;
            *(float4*)(out + b * Hh + c4) = s;
        }
    }
}

// ---------------- launch ----------------
extern "C" void kernel_launch(void* const* d_in, const int* in_sizes, int n_in,
                              void* d_out, int out_size) {
    const float* query  = (const float*)d_in[0];
    const float* key    = (const float*)d_in[1];
    const float* value  = (const float*)d_in[2];
    const float* W_attn = (const float*)d_in[3];
    const float* b_attn = (const float*)d_in[4];
    const float* v      = (const float*)d_in[5];
    float* out = (float*)d_out;

    cudaFuncSetAttribute(k_scores_mma, cudaFuncAttributeMaxDynamicSharedMemorySize, SMEM_BYTES);

    k_prep<<<272, 256>>>(W_attn, query, b_attn);
    k_scores_mma<<<NCTA, 512, SMEM_BYTES>>>(key, v, out);
    k_context<<<Bb * 64, 256>>>(value, out);
}